// round 8
// baseline (speedup 1.0000x reference)
#include <cuda_runtime.h>
#include <cuda_bf16.h>
#include <mma.h>
#include <math.h>
#include <stdint.h>

using namespace nvcuda;

#define SRCL  50
#define NB    128
#define TRGV  30000
#define NPV   30080
#define NCB   235
#define DST   39
#define GROWS 4992

// ----------------------------- device scratch -------------------------------
__device__ __align__(16) float          g_xin[2*SRCL*NB*256];
__device__ __align__(16) float          g_encout[SRCL*NB*128];
__device__ __align__(16) float          g_h0[NB*128];
__device__ __align__(16) float          g_c0[NB*128];
__device__ __align__(16) float          g_dpre[DST*NB*512];
__device__ __align__(16) __nv_bfloat16  g_hall[GROWS*128];
__device__ __align__(16) __nv_bfloat16  g_genW[NPV*128];
__device__ __align__(16) float          g_genb[NPV];
__device__ __align__(16) unsigned       g_Wip[64*128];     // attn_Wi  [k2][d]
__device__ __align__(16) unsigned       g_Wop[128*128];    // attn_Wo  [k2][j]
__device__ __align__(16) unsigned       g_whhp[64*512];    // dec_w_hh [k2][j]
__device__ __align__(16) unsigned       g_wihAp[64*512];   // dec_w_ih[:, :128] [k2][j]
__device__ __align__(16) unsigned       g_ewhh[2*32*256];  // enc_w_hh packed [dir][k2][j]
__device__ __align__(16) float          g_part[NCB*GROWS];
__device__ __align__(16) float          g_lse[GROWS];

// ----------------------------- helpers --------------------------------------
__device__ __forceinline__ unsigned pk2(float a, float b){
    __nv_bfloat162 h = __floats2bfloat162_rn(a, b);
    return *reinterpret_cast<unsigned*>(&h);
}
__device__ __forceinline__ float2 up2(unsigned u){
    __nv_bfloat162 h = *reinterpret_cast<__nv_bfloat162*>(&u);
    return __bfloat1622float2(h);
}
__device__ __forceinline__ float sigf(float x){
    return __fdividef(1.f, 1.f + __expf(-x));
}
__device__ __forceinline__ float tanh_(float x){
    float xc = fminf(15.f, fmaxf(-15.f, x));
    float e  = __expf(2.f*xc);
    return __fdividef(e - 1.f, e + 1.f);
}

// ----------------------------- weight packing -------------------------------
__global__ void k_pack_small(const float* __restrict__ Wi, const float* __restrict__ Wo,
                             const float* __restrict__ dwhh, const float* __restrict__ dwih,
                             const float* __restrict__ ewf, const float* __restrict__ ewb)
{
    int idx = blockIdx.x*256 + threadIdx.x;
    if(idx < 8192){ int k2=idx>>7, d=idx&127;
        g_Wip[idx] = pk2(Wi[d*128+2*k2], Wi[d*128+2*k2+1]); return; }
    idx -= 8192;
    if(idx < 16384){ int k2=idx>>7, j=idx&127;
        g_Wop[idx] = pk2(Wo[j*256+2*k2], Wo[j*256+2*k2+1]); return; }
    idx -= 16384;
    if(idx < 32768){ int k2=idx>>9, j=idx&511;
        g_whhp[idx] = pk2(dwhh[j*128+2*k2], dwhh[j*128+2*k2+1]); return; }
    idx -= 32768;
    if(idx < 32768){ int k2=idx>>9, j=idx&511;
        g_wihAp[idx] = pk2(dwih[j*158+2*k2], dwih[j*158+2*k2+1]); return; }
    idx -= 32768;
    if(idx < 16384){ int dir=idx>>13, r=idx&8191, k2=r>>8, j=r&255;
        const float* w = dir ? ewb : ewf;
        g_ewhh[dir*8192 + k2*256 + j] = pk2(w[j*64+2*k2], w[j*64+2*k2+1]); return; }
}

__global__ void k_pack_gen(const float* __restrict__ genW, const float* __restrict__ genb)
{
    int idx = blockIdx.x*256 + threadIdx.x;            // over NPV*128
    if(idx >= NPV*128) return;
    int n = idx>>7, k = idx&127;
    g_genW[idx] = __float2bfloat16(n < TRGV ? genW[n*128+k] : 0.f);
    if(idx < NPV) g_genb[idx] = (idx < TRGV) ? genb[idx] : -1e30f;
}

// ------------------------ encoder input gates (time-parallel) ----------------
__global__ void k_embpre(const int* __restrict__ src, const float* __restrict__ EEMB,
                         const float* __restrict__ wf, const float* __restrict__ wb,
                         const float* __restrict__ bf, const float* __restrict__ bb)
{
    __shared__ float emb[32];
    int bi = blockIdx.x; int dir = bi / SRCL, s = bi % SRCL;
    int j = threadIdx.x;                                // 0..255 gate row
    const float* w  = dir ? wb : wf;
    const float* bs = dir ? bb : bf;
    float wr[30];
    #pragma unroll
    for(int e=0;e<30;e++) wr[e] = w[j*30+e];
    float bj = bs[j];
    for(int b=0;b<NB;b++){
        __syncthreads();
        if(j < 30){ int tok = src[s*NB+b]; emb[j] = EEMB[tok*30+j]; }
        __syncthreads();
        float a = bj;
        #pragma unroll
        for(int e=0;e<30;e++) a += wr[e]*emb[e];
        g_xin[((dir*SRCL+s)*NB+b)*256 + j] = a;
    }
}

// --------------- decoder embedding gate part + bias (time-parallel) ----------
__global__ void k_dpre(const int* __restrict__ trg, const float* __restrict__ DEMB,
                       const float* __restrict__ dwih, const float* __restrict__ db)
{
    __shared__ float emb[32];
    int t = blockIdx.x;                                 // 0..38 (teacher step)
    int j = threadIdx.x;                                // 0..511 gate row
    float wr[30];
    #pragma unroll
    for(int e=0;e<30;e++) wr[e] = dwih[j*158 + 128 + e];
    float bj = db[j];
    for(int b=0;b<NB;b++){
        __syncthreads();
        if(j < 30){ int tok = trg[t*NB+b]; emb[j] = DEMB[tok*30+j]; }
        __syncthreads();
        float a = bj;
        #pragma unroll
        for(int e=0;e<30;e++) a += wr[e]*emb[e];
        g_dpre[(t*NB+b)*512 + j] = a;
    }
}

// ------------------------------- encoder recurrence --------------------------
// 128 CTAs (one per batch element), 256 threads. smem: packed whh (64KB)+state.
__global__ void k_enc()
{
    extern __shared__ char sm[];
    unsigned* ws = (unsigned*)sm;                       // 16384 u (64KB)
    float* hs = (float*)(sm + 65536);                   // [dir*64+d] 128
    float* cs = hs + 128;                               // 128
    float* gb = cs + 128;                               // 512
    int b = blockIdx.x, tid = threadIdx.x;

    { uint4* d4=(uint4*)ws; const uint4* s4=(const uint4*)g_ewhh;
      for(int i=tid;i<4096;i+=256) d4[i]=s4[i]; }
    if(tid < 128){ hs[tid]=0.f; cs[tid]=0.f; }
    __syncthreads();

    for(int t=0;t<SRCL;t++){
        float af = g_xin[((0*SRCL + t        )*NB+b)*256 + tid];
        float ab = g_xin[((1*SRCL + (SRCL-1-t))*NB+b)*256 + tid];
        #pragma unroll 8
        for(int k2=0;k2<32;k2++){
            float h0 = hs[2*k2], h1 = hs[2*k2+1];
            float2 wf2 = up2(ws[k2*256 + tid]);
            af += h0*wf2.x + h1*wf2.y;
            float g0 = hs[64+2*k2], g1 = hs[64+2*k2+1];
            float2 wb2 = up2(ws[8192 + k2*256 + tid]);
            ab += g0*wb2.x + g1*wb2.y;
        }
        gb[tid] = af; gb[256+tid] = ab;
        __syncthreads();
        if(tid < 128){
            int dir = tid>>6, d = tid&63;
            float* g = gb + dir*256;
            float iv=g[d], fv=g[64+d], gv=g[128+d], ov=g[192+d];
            float cn = sigf(fv)*cs[dir*64+d] + sigf(iv)*tanh_(gv);
            float hn = sigf(ov)*tanh_(cn);
            cs[dir*64+d]=cn; hs[dir*64+d]=hn;
            int s_out = dir ? (SRCL-1-t) : t;
            g_encout[(s_out*NB+b)*128 + dir*64 + d] = hn;
        }
        __syncthreads();
    }
    if(tid < 64){
        g_h0[b*128+2*tid]   = hs[tid];
        g_h0[b*128+2*tid+1] = hs[64+tid];
        g_c0[b*128+2*tid]   = cs[tid];
        g_c0[b*128+2*tid+1] = cs[64+tid];
    }
}

// ------------------------------- decoder recurrence --------------------------
// 128 CTAs (one per batch element), 256 threads.
// smem: whh bf16 (128KB) + Wo bf16 (64KB) + enc_out slice (25.6KB) + state.
__global__ void k_dec()
{
    extern __shared__ char sm[];
    unsigned* whh  = (unsigned*)sm;                 // 32768 u  @0
    unsigned* wop  = (unsigned*)(sm + 131072);      // 16384 u
    float*    encs = (float*)  (sm + 196608);       // 6400 f  [s*128+d]
    float*    h    = (float*)  (sm + 222208);       // 128
    float*    c    = h   + 128;
    float*    semi = c   + 128;
    float*    st   = semi+ 128;
    float*    ct   = st  + 128;
    float*    es   = ct  + 128;                     // 64
    float*    sc   = es  + 64;                      // 64
    float*    gb   = sc  + 64;                      // 512
    int b = blockIdx.x, tid = threadIdx.x;
    int lane = tid & 31, w = tid >> 5;

    { uint4* d4=(uint4*)whh; const uint4* s4=(const uint4*)g_whhp;
      for(int i=tid;i<8192;i+=256) d4[i]=s4[i]; }
    { uint4* d4=(uint4*)wop; const uint4* s4=(const uint4*)g_Wop;
      for(int i=tid;i<4096;i+=256) d4[i]=s4[i]; }
    { float4* d4=(float4*)encs; const float4* s4=(const float4*)g_encout;
      for(int i=tid;i<1600;i+=256){ int s=i>>5, r=i&31; d4[i]=s4[(s*NB+b)*32 + r]; } }
    if(tid < 128){ h[tid]=g_h0[b*128+tid]; c[tid]=g_c0[b*128+tid]; }
    __syncthreads();

    for(int t=0;t<DST;t++){
        // 1) semi = h @ Wi.T
        if(tid < 128){
            float a = 0.f;
            #pragma unroll 8
            for(int k2=0;k2<64;k2++){
                float2 w2 = up2(__ldg(&g_Wip[k2*128 + tid]));
                a += h[2*k2]*w2.x + h[2*k2+1]*w2.y;
            }
            semi[tid] = a;
        }
        __syncthreads();
        // 2) attention scores
        for(int s=w; s<SRCL; s+=8){
            const float* er = encs + s*128;
            float a = er[lane]*semi[lane] + er[lane+32]*semi[lane+32]
                    + er[lane+64]*semi[lane+64] + er[lane+96]*semi[lane+96];
            #pragma unroll
            for(int o=16;o>0;o>>=1) a += __shfl_xor_sync(0xffffffffu, a, o);
            if(lane==0) es[s] = a;
        }
        __syncthreads();
        // 3) softmax over 50 (warp 0)
        if(w == 0){
            float v0 = (lane    < SRCL) ? es[lane]    : -1e30f;
            float v1 = (lane+32 < SRCL) ? es[lane+32] : -1e30f;
            float m = fmaxf(v0, v1);
            #pragma unroll
            for(int o=16;o>0;o>>=1) m = fmaxf(m, __shfl_xor_sync(0xffffffffu, m, o));
            float e0 = (lane    < SRCL) ? __expf(v0-m) : 0.f;
            float e1 = (lane+32 < SRCL) ? __expf(v1-m) : 0.f;
            float ssum = e0 + e1;
            #pragma unroll
            for(int o=16;o>0;o>>=1) ssum += __shfl_xor_sync(0xffffffffu, ssum, o);
            float inv = __fdividef(1.f, ssum);
            if(lane    < SRCL) sc[lane]    = e0*inv;
            if(lane+32 < SRCL) sc[lane+32] = e1*inv;
        }
        __syncthreads();
        // 4) s_tilde
        if(tid < 128){
            float a = 0.f;
            #pragma unroll 10
            for(int s=0;s<SRCL;s++) a += sc[s]*encs[s*128 + tid];
            st[tid] = a;
        }
        __syncthreads();
        // 5) c_t = tanh([s_tilde,h] @ Wo.T)
        if(tid < 128){
            float a = 0.f;
            #pragma unroll 8
            for(int k2=0;k2<64;k2++){
                float2 w2 = up2(wop[k2*128 + tid]);
                a += st[2*k2]*w2.x + st[2*k2+1]*w2.y;
            }
            #pragma unroll 8
            for(int k2=0;k2<64;k2++){
                float2 w2 = up2(wop[(64+k2)*128 + tid]);
                a += h[2*k2]*w2.x + h[2*k2+1]*w2.y;
            }
            ct[tid] = tanh_(a);
        }
        __syncthreads();
        // 6) gates g = pre + c_t@w_ihA.T + h@w_hh.T (2 rows/thread)
        {
            const float* pre = g_dpre + (t*NB+b)*512;
            float a0 = __ldg(&pre[tid]);
            float a1 = __ldg(&pre[tid+256]);
            #pragma unroll 4
            for(int k2=0;k2<64;k2++){
                float x0 = ct[2*k2], x1 = ct[2*k2+1];
                float2 wA0 = up2(__ldg(&g_wihAp[k2*512 + tid]));
                float2 wA1 = up2(__ldg(&g_wihAp[k2*512 + tid + 256]));
                a0 += x0*wA0.x + x1*wA0.y;
                a1 += x0*wA1.x + x1*wA1.y;
                float y0 = h[2*k2], y1 = h[2*k2+1];
                float2 wH0 = up2(whh[k2*512 + tid]);
                float2 wH1 = up2(whh[k2*512 + tid + 256]);
                a0 += y0*wH0.x + y1*wH0.y;
                a1 += y0*wH1.x + y1*wH1.y;
            }
            gb[tid] = a0; gb[tid+256] = a1;
        }
        __syncthreads();
        // 7) LSTM update
        if(tid < 128){
            float iv=gb[tid], fv=gb[128+tid], gv=gb[256+tid], ov=gb[384+tid];
            float cn = sigf(fv)*c[tid] + sigf(iv)*tanh_(gv);
            float hn = sigf(ov)*tanh_(cn);
            c[tid]=cn; h[tid]=hn;
            g_hall[(t*NB+b)*128 + tid] = __float2bfloat16(hn);
        }
        __syncthreads();
    }
}

// ------------------------------- generator GEMM ------------------------------
// CTA tile: 128(M) x 128(N), K=128 full. smem: A/B bf16 (68KB) reused as C f32.
__device__ __forceinline__ void gemm_tile(char* sm, int mb, int nb)
{
    __nv_bfloat16* As = (__nv_bfloat16*)sm;             // 128 x 136
    __nv_bfloat16* Bs = As + 128*136;                   // 128 x 136
    int tid = threadIdx.x;
    for(int i=tid;i<2048;i+=256){
        int r=i>>4, cc=i&15;
        *(uint4*)(As + r*136 + cc*8) = *(const uint4*)(g_hall + (mb*128+r)*128 + cc*8);
    }
    for(int i=tid;i<2048;i+=256){
        int r=i>>4, cc=i&15;
        *(uint4*)(Bs + r*136 + cc*8) = *(const uint4*)(g_genW + (nb*128+r)*128 + cc*8);
    }
    __syncthreads();

    wmma::fragment<wmma::matrix_a,16,16,16,__nv_bfloat16,wmma::row_major> af[2];
    wmma::fragment<wmma::matrix_b,16,16,16,__nv_bfloat16,wmma::col_major> bf[4];
    wmma::fragment<wmma::accumulator,16,16,16,float> acc[2][4];
    #pragma unroll
    for(int i=0;i<2;i++)
        #pragma unroll
        for(int j=0;j<4;j++) wmma::fill_fragment(acc[i][j], 0.f);
    int w = tid>>5, wm = w>>1, wn = w&1;
    #pragma unroll
    for(int kk=0;kk<8;kk++){
        #pragma unroll
        for(int i=0;i<2;i++)
            wmma::load_matrix_sync(af[i], As + (wm*32+i*16)*136 + kk*16, 136);
        #pragma unroll
        for(int j=0;j<4;j++)
            wmma::load_matrix_sync(bf[j], Bs + (wn*64+j*16)*136 + kk*16, 136);
        #pragma unroll
        for(int i=0;i<2;i++)
            #pragma unroll
            for(int j=0;j<4;j++)
                wmma::mma_sync(acc[i][j], af[i], bf[j], acc[i][j]);
    }
    __syncthreads();                                    // smem reuse barrier
    float* Cs = (float*)sm;                             // 128 x 132
    #pragma unroll
    for(int i=0;i<2;i++)
        #pragma unroll
        for(int j=0;j<4;j++)
            wmma::store_matrix_sync(Cs + (wm*32+i*16)*132 + wn*64 + j*16,
                                    acc[i][j], 132, wmma::mem_row_major);
    __syncthreads();
}

__global__ void k_gen1()
{
    extern __shared__ char sm[];
    int mb = blockIdx.y, nb = blockIdx.x;
    gemm_tile(sm, mb, nb);
    float* Cs = (float*)sm;
    int tid = threadIdx.x, r = tid>>1, ch = tid&1;
    const float* bb  = g_genb + nb*128 + ch*64;
    const float* row = Cs + r*132 + ch*64;
    float s = 0.f;
    #pragma unroll 8
    for(int cc=0;cc<64;cc++) s += __expf(row[cc] + __ldg(&bb[cc]));
    s += __shfl_xor_sync(0xffffffffu, s, 1);
    if(ch == 0) g_part[nb*GROWS + mb*128 + r] = s;
}

__global__ void k_lse()
{
    int m = blockIdx.x*256 + threadIdx.x;
    if(m >= GROWS) return;
    float s = 0.f;
    for(int nb=0;nb<NCB;nb++) s += g_part[nb*GROWS + m];
    g_lse[m] = logf(s);
}

__global__ void k_gen2(float* __restrict__ out)
{
    extern __shared__ char sm[];
    int mb = blockIdx.y, nb = blockIdx.x;
    gemm_tile(sm, mb, nb);
    float* Cs = (float*)sm;
    int tid = threadIdx.x, r = tid>>1, ch = tid&1;
    int col0 = nb*128 + ch*64;
    if(col0 >= TRGV) return;
    float l = g_lse[mb*128 + r];
    const float* bb  = g_genb + col0;
    const float* row = Cs + r*132 + ch*64;
    float* orow = out + ((size_t)((mb+1)*NB + r))*TRGV + col0;
    int lim = TRGV - col0; if(lim > 64) lim = 64;       // 64 or 48
    for(int cc=0; cc<lim; cc+=4){
        float4 v;
        v.x = row[cc+0] + __ldg(&bb[cc+0]) - l;
        v.y = row[cc+1] + __ldg(&bb[cc+1]) - l;
        v.z = row[cc+2] + __ldg(&bb[cc+2]) - l;
        v.w = row[cc+3] + __ldg(&bb[cc+3]) - l;
        *(float4*)(orow + cc) = v;
    }
}

__global__ void k_row0(float* __restrict__ out)
{
    int i = blockIdx.x*256 + threadIdx.x;               // over 960000 float4
    if(i >= NB*TRGV/4) return;
    int r = i % (TRGV/4);
    float4 v = make_float4(-1.f,-1.f,-1.f,-1.f);
    if(r == 0) v.z = 0.f;                               // col 2
    ((float4*)out)[i] = v;
}

// ----------------------------- launcher --------------------------------------
extern "C" void kernel_launch(void* const* d_in, const int* in_sizes, int n_in,
                              void* d_out, int out_size)
{
    const int*   src  = (const int*)  d_in[0];
    const int*   trg  = (const int*)  d_in[1];
    const float* EEMB = (const float*)d_in[3];
    const float* DEMB = (const float*)d_in[4];
    const float* ewf  = (const float*)d_in[5];
    const float* ewhf = (const float*)d_in[6];
    const float* ebf  = (const float*)d_in[7];
    const float* ewb  = (const float*)d_in[8];
    const float* ewhb = (const float*)d_in[9];
    const float* ebb  = (const float*)d_in[10];
    const float* Wi   = (const float*)d_in[11];
    const float* Wo   = (const float*)d_in[12];
    const float* dwih = (const float*)d_in[13];
    const float* dwhh = (const float*)d_in[14];
    const float* db   = (const float*)d_in[15];
    const float* genW = (const float*)d_in[16];
    const float* genb = (const float*)d_in[17];
    float* out = (float*)d_out;

    cudaFuncSetAttribute(k_enc,  cudaFuncAttributeMaxDynamicSharedMemorySize, 68608);
    cudaFuncSetAttribute(k_dec,  cudaFuncAttributeMaxDynamicSharedMemorySize, 227328);
    cudaFuncSetAttribute(k_gen1, cudaFuncAttributeMaxDynamicSharedMemorySize, 69632);
    cudaFuncSetAttribute(k_gen2, cudaFuncAttributeMaxDynamicSharedMemorySize, 69632);

    k_pack_small<<<416, 256>>>(Wi, Wo, dwhh, dwih, ewhf, ewhb);
    k_pack_gen<<<(NPV*128+255)/256, 256>>>(genW, genb);
    k_embpre<<<100, 256>>>(src, EEMB, ewf, ewb, ebf, ebb);
    k_dpre<<<DST, 512>>>(trg, DEMB, dwih, db);
    k_enc<<<NB, 256, 68608>>>();
    k_dec<<<NB, 256, 227328>>>();
    k_gen1<<<dim3(NCB, DST), 256, 69632>>>();
    k_lse<<<(GROWS+255)/256, 256>>>();
    k_gen2<<<dim3(NCB, DST), 256, 69632>>>(out);
    k_row0<<<(NB*TRGV/4+255)/256, 256>>>(out);
}

// round 11
// speedup vs baseline: 1.1883x; 1.1883x over previous
#include <cuda_runtime.h>
#include <cuda_bf16.h>
#include <math.h>
#include <stdint.h>

#define SRCL  50
#define NB    128
#define TRGV  30000
#define NPV   30080
#define NCB   235
#define DST   39
#define GROWS 4992

// ----------------------------- device scratch -------------------------------
__device__ __align__(16) float          g_xin[2*SRCL*NB*256];
__device__ __align__(16) float          g_encout[SRCL*NB*128];
__device__ __align__(16) float          g_h0[NB*128];
__device__ __align__(16) float          g_c0[NB*128];
__device__ __align__(16) float          g_dpre[DST*NB*512];
__device__ __align__(16) __nv_bfloat16  g_hall[GROWS*128];
__device__ __align__(16) __nv_bfloat16  g_genW[NPV*128];
__device__ __align__(16) float          g_genb[NPV];
__device__ __align__(16) unsigned       g_Wip[64*128];     // attn_Wi  [k2][d]
__device__ __align__(16) unsigned       g_Wop[128*128];    // attn_Wo  [k2][j]
__device__ __align__(16) unsigned       g_whhp[64*512];    // dec_w_hh [k2][j]
__device__ __align__(16) unsigned       g_wihAp[64*512];   // dec_w_ih[:, :128] [k2][j]
__device__ __align__(16) unsigned       g_ewhh[2*32*256];  // enc_w_hh packed [dir][k2][j]
__device__ __align__(16) float          g_part[NCB*GROWS];
__device__ __align__(16) float          g_lse[GROWS];

// ----------------------------- helpers --------------------------------------
__device__ __forceinline__ unsigned pk2(float a, float b){
    __nv_bfloat162 h = __floats2bfloat162_rn(a, b);
    return *reinterpret_cast<unsigned*>(&h);
}
__device__ __forceinline__ float2 up2(unsigned u){
    __nv_bfloat162 h = *reinterpret_cast<__nv_bfloat162*>(&u);
    return __bfloat1622float2(h);
}
__device__ __forceinline__ float sigf(float x){
    return __fdividef(1.f, 1.f + __expf(-x));
}
__device__ __forceinline__ float tanh_(float x){
    float xc = fminf(15.f, fmaxf(-15.f, x));
    float e  = __expf(2.f*xc);
    return __fdividef(e - 1.f, e + 1.f);
}
__device__ __forceinline__ void mma16816(float* d, const unsigned* a, const unsigned* b){
    asm volatile("mma.sync.aligned.m16n8k16.row.col.f32.bf16.bf16.f32 "
        "{%0,%1,%2,%3}, {%4,%5,%6,%7}, {%8,%9}, {%0,%1,%2,%3};"
        : "+f"(d[0]), "+f"(d[1]), "+f"(d[2]), "+f"(d[3])
        : "r"(a[0]), "r"(a[1]), "r"(a[2]), "r"(a[3]), "r"(b[0]), "r"(b[1]));
}

// ----------------------------- weight packing -------------------------------
__global__ void k_pack_small(const float* __restrict__ Wi, const float* __restrict__ Wo,
                             const float* __restrict__ dwhh, const float* __restrict__ dwih,
                             const float* __restrict__ ewf, const float* __restrict__ ewb)
{
    int idx = blockIdx.x*256 + threadIdx.x;
    if(idx < 8192){ int k2=idx>>7, d=idx&127;
        g_Wip[idx] = pk2(Wi[d*128+2*k2], Wi[d*128+2*k2+1]); return; }
    idx -= 8192;
    if(idx < 16384){ int k2=idx>>7, j=idx&127;
        g_Wop[idx] = pk2(Wo[j*256+2*k2], Wo[j*256+2*k2+1]); return; }
    idx -= 16384;
    if(idx < 32768){ int k2=idx>>9, j=idx&511;
        g_whhp[idx] = pk2(dwhh[j*128+2*k2], dwhh[j*128+2*k2+1]); return; }
    idx -= 32768;
    if(idx < 32768){ int k2=idx>>9, j=idx&511;
        g_wihAp[idx] = pk2(dwih[j*158+2*k2], dwih[j*158+2*k2+1]); return; }
    idx -= 32768;
    if(idx < 16384){ int dir=idx>>13, r=idx&8191, k2=r>>8, j=r&255;
        const float* w = dir ? ewb : ewf;
        g_ewhh[dir*8192 + k2*256 + j] = pk2(w[j*64+2*k2], w[j*64+2*k2+1]); return; }
}

__global__ void k_pack_gen(const float* __restrict__ genW, const float* __restrict__ genb)
{
    int idx = blockIdx.x*256 + threadIdx.x;            // over NPV*128
    if(idx >= NPV*128) return;
    int n = idx>>7, k = idx&127;
    g_genW[idx] = __float2bfloat16(n < TRGV ? genW[n*128+k] : 0.f);
    if(idx < NPV) g_genb[idx] = (idx < TRGV) ? genb[idx] : -1e30f;
}

// ------------------------ encoder input gates (time & batch parallel) --------
__global__ void k_embpre(const int* __restrict__ src, const float* __restrict__ EEMB,
                         const float* __restrict__ wf, const float* __restrict__ wb,
                         const float* __restrict__ bf_, const float* __restrict__ bb_)
{
    __shared__ float emb[16][32];
    int bi = blockIdx.y; int dir = bi / SRCL, s = bi % SRCL;
    int b0 = blockIdx.x * 16;
    int j = threadIdx.x;                                // 0..255 gate row
    const float* w  = dir ? wb : wf;
    float wr[30];
    #pragma unroll
    for(int e=0;e<30;e++) wr[e] = w[j*30+e];
    float bj = (dir ? bb_ : bf_)[j];
    for(int i=j;i<480;i+=256){
        int q=i/30, e=i%30; int tok = src[s*NB + b0 + q];
        emb[q][e] = EEMB[tok*30+e];
    }
    __syncthreads();
    #pragma unroll 4
    for(int q=0;q<16;q++){
        float a = bj;
        #pragma unroll
        for(int e=0;e<30;e++) a += wr[e]*emb[q][e];
        g_xin[((dir*SRCL+s)*NB + b0 + q)*256 + j] = a;
    }
}

// --------------- decoder embedding gate part + bias (parallel) ---------------
__global__ void k_dpre(const int* __restrict__ trg, const float* __restrict__ DEMB,
                       const float* __restrict__ dwih, const float* __restrict__ db)
{
    __shared__ float emb[16][32];
    int t = blockIdx.y;                                 // 0..38 teacher step
    int b0 = blockIdx.x * 16;
    int j = threadIdx.x;                                // 0..511 gate row
    float wr[30];
    #pragma unroll
    for(int e=0;e<30;e++) wr[e] = dwih[j*158 + 128 + e];
    float bj = db[j];
    for(int i=j;i<480;i+=512){
        int q=i/30, e=i%30; int tok = trg[t*NB + b0 + q];
        emb[q][e] = DEMB[tok*30+e];
    }
    __syncthreads();
    #pragma unroll 4
    for(int q=0;q<16;q++){
        float a = bj;
        #pragma unroll
        for(int e=0;e<30;e++) a += wr[e]*emb[q][e];
        g_dpre[(t*NB + b0 + q)*512 + j] = a;
    }
}

// ------------------------------- encoder recurrence --------------------------
__global__ void k_enc()
{
    extern __shared__ char sm[];
    unsigned* ws = (unsigned*)sm;                       // 16384 u (64KB)
    float* hs = (float*)(sm + 65536);                   // 128
    float* cs = hs + 128;                               // 128
    float* gb = cs + 128;                               // 512
    int b = blockIdx.x, tid = threadIdx.x;

    { uint4* d4=(uint4*)ws; const uint4* s4=(const uint4*)g_ewhh;
      for(int i=tid;i<4096;i+=256) d4[i]=s4[i]; }
    if(tid < 128){ hs[tid]=0.f; cs[tid]=0.f; }
    __syncthreads();

    for(int t=0;t<SRCL;t++){
        float af = g_xin[((0*SRCL + t        )*NB+b)*256 + tid];
        float ab = g_xin[((1*SRCL + (SRCL-1-t))*NB+b)*256 + tid];
        #pragma unroll 8
        for(int k2=0;k2<32;k2++){
            float h0 = hs[2*k2], h1 = hs[2*k2+1];
            float2 wf2 = up2(ws[k2*256 + tid]);
            af += h0*wf2.x + h1*wf2.y;
            float g0 = hs[64+2*k2], g1 = hs[64+2*k2+1];
            float2 wb2 = up2(ws[8192 + k2*256 + tid]);
            ab += g0*wb2.x + g1*wb2.y;
        }
        gb[tid] = af; gb[256+tid] = ab;
        __syncthreads();
        if(tid < 128){
            int dir = tid>>6, d = tid&63;
            float* g = gb + dir*256;
            float iv=g[d], fv=g[64+d], gv=g[128+d], ov=g[192+d];
            float cn = sigf(fv)*cs[dir*64+d] + sigf(iv)*tanh_(gv);
            float hn = sigf(ov)*tanh_(cn);
            cs[dir*64+d]=cn; hs[dir*64+d]=hn;
            int s_out = dir ? (SRCL-1-t) : t;
            g_encout[(s_out*NB+b)*128 + dir*64 + d] = hn;
        }
        __syncthreads();
    }
    if(tid < 64){
        g_h0[b*128+2*tid]   = hs[tid];
        g_h0[b*128+2*tid+1] = hs[64+tid];
        g_c0[b*128+2*tid]   = cs[tid];
        g_c0[b*128+2*tid+1] = cs[64+tid];
    }
}

// ------------------------------- decoder recurrence --------------------------
__global__ void k_dec()
{
    extern __shared__ char sm[];
    unsigned* whh  = (unsigned*)sm;                 // 32768 u  @0
    unsigned* wop  = (unsigned*)(sm + 131072);      // 16384 u
    float*    encs = (float*)  (sm + 196608);       // 6400 f
    float*    h    = (float*)  (sm + 222208);       // 128
    float*    c    = h   + 128;
    float*    semi = c   + 128;
    float*    st   = semi+ 128;
    float*    ct   = st  + 128;
    float*    es   = ct  + 128;                     // 64
    float*    sc   = es  + 64;                      // 64
    float*    gb   = sc  + 64;                      // 512
    int b = blockIdx.x, tid = threadIdx.x;
    int lane = tid & 31, w = tid >> 5;

    { uint4* d4=(uint4*)whh; const uint4* s4=(const uint4*)g_whhp;
      for(int i=tid;i<8192;i+=256) d4[i]=s4[i]; }
    { uint4* d4=(uint4*)wop; const uint4* s4=(const uint4*)g_Wop;
      for(int i=tid;i<4096;i+=256) d4[i]=s4[i]; }
    { float4* d4=(float4*)encs; const float4* s4=(const float4*)g_encout;
      for(int i=tid;i<1600;i+=256){ int s=i>>5, r=i&31; d4[i]=s4[(s*NB+b)*32 + r]; } }
    if(tid < 128){ h[tid]=g_h0[b*128+tid]; c[tid]=g_c0[b*128+tid]; }
    __syncthreads();

    for(int t=0;t<DST;t++){
        if(tid < 128){
            float a = 0.f;
            #pragma unroll 8
            for(int k2=0;k2<64;k2++){
                float2 w2 = up2(__ldg(&g_Wip[k2*128 + tid]));
                a += h[2*k2]*w2.x + h[2*k2+1]*w2.y;
            }
            semi[tid] = a;
        }
        __syncthreads();
        for(int s=w; s<SRCL; s+=8){
            const float* er = encs + s*128;
            float a = er[lane]*semi[lane] + er[lane+32]*semi[lane+32]
                    + er[lane+64]*semi[lane+64] + er[lane+96]*semi[lane+96];
            #pragma unroll
            for(int o=16;o>0;o>>=1) a += __shfl_xor_sync(0xffffffffu, a, o);
            if(lane==0) es[s] = a;
        }
        __syncthreads();
        if(w == 0){
            float v0 = (lane    < SRCL) ? es[lane]    : -1e30f;
            float v1 = (lane+32 < SRCL) ? es[lane+32] : -1e30f;
            float m = fmaxf(v0, v1);
            #pragma unroll
            for(int o=16;o>0;o>>=1) m = fmaxf(m, __shfl_xor_sync(0xffffffffu, m, o));
            float e0 = (lane    < SRCL) ? __expf(v0-m) : 0.f;
            float e1 = (lane+32 < SRCL) ? __expf(v1-m) : 0.f;
            float ssum = e0 + e1;
            #pragma unroll
            for(int o=16;o>0;o>>=1) ssum += __shfl_xor_sync(0xffffffffu, ssum, o);
            float inv = __fdividef(1.f, ssum);
            if(lane    < SRCL) sc[lane]    = e0*inv;
            if(lane+32 < SRCL) sc[lane+32] = e1*inv;
        }
        __syncthreads();
        if(tid < 128){
            float a = 0.f;
            #pragma unroll 10
            for(int s=0;s<SRCL;s++) a += sc[s]*encs[s*128 + tid];
            st[tid] = a;
        }
        __syncthreads();
        if(tid < 128){
            float a = 0.f;
            #pragma unroll 8
            for(int k2=0;k2<64;k2++){
                float2 w2 = up2(wop[k2*128 + tid]);
                a += st[2*k2]*w2.x + st[2*k2+1]*w2.y;
            }
            #pragma unroll 8
            for(int k2=0;k2<64;k2++){
                float2 w2 = up2(wop[(64+k2)*128 + tid]);
                a += h[2*k2]*w2.x + h[2*k2+1]*w2.y;
            }
            ct[tid] = tanh_(a);
        }
        __syncthreads();
        {
            const float* pre = g_dpre + (t*NB+b)*512;
            float a0 = __ldg(&pre[tid]);
            float a1 = __ldg(&pre[tid+256]);
            #pragma unroll 4
            for(int k2=0;k2<64;k2++){
                float x0 = ct[2*k2], x1 = ct[2*k2+1];
                float2 wA0 = up2(__ldg(&g_wihAp[k2*512 + tid]));
                float2 wA1 = up2(__ldg(&g_wihAp[k2*512 + tid + 256]));
                a0 += x0*wA0.x + x1*wA0.y;
                a1 += x0*wA1.x + x1*wA1.y;
                float y0 = h[2*k2], y1 = h[2*k2+1];
                float2 wH0 = up2(whh[k2*512 + tid]);
                float2 wH1 = up2(whh[k2*512 + tid + 256]);
                a0 += y0*wH0.x + y1*wH0.y;
                a1 += y0*wH1.x + y1*wH1.y;
            }
            gb[tid] = a0; gb[tid+256] = a1;
        }
        __syncthreads();
        if(tid < 128){
            float iv=gb[tid], fv=gb[128+tid], gv=gb[256+tid], ov=gb[384+tid];
            float cn = sigf(fv)*c[tid] + sigf(iv)*tanh_(gv);
            float hn = sigf(ov)*tanh_(cn);
            c[tid]=cn; h[tid]=hn;
            g_hall[(t*NB+b)*128 + tid] = __float2bfloat16(hn);
        }
        __syncthreads();
    }
}

// ------------------- generator GEMM (mma.sync, single pass) ------------------
// CTA: 128(M) x 128(N), K=128 resident. smem: A,B bf16 pitch-136 (69.6KB),
// reused as C f32 pitch-132 (67.6KB). 8 warps = 4(m) x 2(n), warp tile 32x64.
#define GP 136
#define CP 132
__global__ void __launch_bounds__(256) k_gen(float* __restrict__ out)
{
    extern __shared__ char sm[];
    __nv_bfloat16* As = (__nv_bfloat16*)sm;
    __nv_bfloat16* Bs = As + 128*GP;
    int tid = threadIdx.x, w = tid>>5, lane = tid&31;
    int mb = blockIdx.y, nb = blockIdx.x;

    const uint4* Asrc = (const uint4*)(g_hall + (size_t)mb*128*128);
    const uint4* Bsrc = (const uint4*)(g_genW + (size_t)nb*128*128);
    for(int i=tid;i<2048;i+=256){
        int r=i>>4, c=i&15;
        *(uint4*)(As + r*GP + c*8) = Asrc[i];
    }
    for(int i=tid;i<2048;i+=256){
        int r=i>>4, c=i&15;
        *(uint4*)(Bs + r*GP + c*8) = Bsrc[i];
    }
    __syncthreads();

    int wm = w & 3, wn = w >> 2;                    // warp grid 4x2
    int m0 = wm*32, n0 = wn*64;
    int lq = lane>>2, lr = lane&3;

    float acc[2][8][4];
    #pragma unroll
    for(int mi=0;mi<2;mi++)
        #pragma unroll
        for(int ni=0;ni<8;ni++)
            #pragma unroll
            for(int q=0;q<4;q++) acc[mi][ni][q] = 0.f;

    const __nv_bfloat16* Ab = As + (m0+lq)*GP + 2*lr;
    const __nv_bfloat16* Bb = Bs + (n0+lq)*GP + 2*lr;

    #pragma unroll
    for(int ks=0;ks<8;ks++){
        int k0 = ks*16;
        unsigned a[2][4];
        #pragma unroll
        for(int mi=0;mi<2;mi++){
            const __nv_bfloat16* p = Ab + mi*16*GP + k0;
            a[mi][0] = *(const unsigned*)(p);
            a[mi][1] = *(const unsigned*)(p + 8*GP);
            a[mi][2] = *(const unsigned*)(p + 8);
            a[mi][3] = *(const unsigned*)(p + 8*GP + 8);
        }
        #pragma unroll
        for(int ni=0;ni<8;ni++){
            unsigned bfr[2];
            const __nv_bfloat16* p = Bb + ni*8*GP + k0;
            bfr[0] = *(const unsigned*)(p);
            bfr[1] = *(const unsigned*)(p + 8);
            mma16816(acc[0][ni], a[0], bfr);
            mma16816(acc[1][ni], a[1], bfr);
        }
    }
    __syncthreads();                                 // before smem reuse as C

    float* Cs = (float*)sm;
    #pragma unroll
    for(int mi=0;mi<2;mi++){
        #pragma unroll
        for(int ni=0;ni<8;ni++){
            float* cr = Cs + (m0+mi*16+lq)*CP + n0 + ni*8 + 2*lr;
            cr[0] = acc[mi][ni][0]; cr[1] = acc[mi][ni][1];
            cr[8*CP] = acc[mi][ni][2]; cr[8*CP+1] = acc[mi][ni][3];
        }
    }
    __syncthreads();

    // epilogue: add bias, write logits, reduce per-row sum(exp)
    int r = tid>>1, hh = tid&1;                      // row 0..127, col half
    const float* bb  = g_genb + nb*128 + hh*64;
    const float* row = Cs + r*CP + hh*64;
    int col0 = nb*128 + hh*64;
    float* orow = out + (size_t)(NB + mb*128 + r)*TRGV + col0;
    float s = 0.f;
    #pragma unroll 4
    for(int c=0;c<64;c+=4){
        float4 v;
        v.x = row[c+0] + __ldg(&bb[c+0]);
        v.y = row[c+1] + __ldg(&bb[c+1]);
        v.z = row[c+2] + __ldg(&bb[c+2]);
        v.w = row[c+3] + __ldg(&bb[c+3]);
        s += __expf(v.x) + __expf(v.y) + __expf(v.z) + __expf(v.w);
        if(col0 + c < TRGV) *(float4*)(orow + c) = v;
    }
    s += __shfl_xor_sync(0xffffffffu, s, 1);
    if(hh == 0) g_part[nb*GROWS + mb*128 + r] = s;
}

__global__ void k_lse()
{
    int m = blockIdx.x*256 + threadIdx.x;
    if(m >= GROWS) return;
    float s = 0.f;
    for(int nb=0;nb<NCB;nb++) s += g_part[nb*GROWS + m];
    g_lse[m] = logf(s);
}

// out[row] -= lse[row] for rows NB..NB+GROWS-1 (streaming)
__global__ void __launch_bounds__(256) k_fix(float* __restrict__ out)
{
    int row = blockIdx.y;                            // 0..GROWS-1
    int c4  = blockIdx.x*256 + threadIdx.x;          // 0..7499
    if(c4 >= TRGV/4) return;
    float l = __ldg(&g_lse[row]);
    float4* p = (float4*)(out + (size_t)(NB + row)*TRGV) + c4;
    float4 v = *p;
    v.x -= l; v.y -= l; v.z -= l; v.w -= l;
    *p = v;
}

__global__ void k_row0(float* __restrict__ out)
{
    int i = blockIdx.x*256 + threadIdx.x;            // over NB*TRGV/4 float4
    if(i >= NB*TRGV/4) return;
    int r = i % (TRGV/4);
    float4 v = make_float4(-1.f,-1.f,-1.f,-1.f);
    if(r == 0) v.z = 0.f;                            // col 2
    ((float4*)out)[i] = v;
}

// ----------------------------- launcher --------------------------------------
extern "C" void kernel_launch(void* const* d_in, const int* in_sizes, int n_in,
                              void* d_out, int out_size)
{
    const int*   src  = (const int*)  d_in[0];
    const int*   trg  = (const int*)  d_in[1];
    const float* EEMB = (const float*)d_in[3];
    const float* DEMB = (const float*)d_in[4];
    const float* ewf  = (const float*)d_in[5];
    const float* ewhf = (const float*)d_in[6];
    const float* ebf  = (const float*)d_in[7];
    const float* ewb  = (const float*)d_in[8];
    const float* ewhb = (const float*)d_in[9];
    const float* ebb  = (const float*)d_in[10];
    const float* Wi   = (const float*)d_in[11];
    const float* Wo   = (const float*)d_in[12];
    const float* dwih = (const float*)d_in[13];
    const float* dwhh = (const float*)d_in[14];
    const float* db   = (const float*)d_in[15];
    const float* genW = (const float*)d_in[16];
    const float* genb = (const float*)d_in[17];
    float* out = (float*)d_out;

    const int GEN_SMEM = 128*GP*2*2;                 // 69632 B

    cudaFuncSetAttribute(k_enc, cudaFuncAttributeMaxDynamicSharedMemorySize, 68608);
    cudaFuncSetAttribute(k_dec, cudaFuncAttributeMaxDynamicSharedMemorySize, 227328);
    cudaFuncSetAttribute(k_gen, cudaFuncAttributeMaxDynamicSharedMemorySize, GEN_SMEM);

    k_pack_small<<<416, 256>>>(Wi, Wo, dwhh, dwih, ewhf, ewhb);
    k_pack_gen<<<(NPV*128+255)/256, 256>>>(genW, genb);
    k_embpre<<<dim3(8, 100), 256>>>(src, EEMB, ewf, ewb, ebf, ebb);
    k_dpre<<<dim3(8, DST), 512>>>(trg, DEMB, dwih, db);
    k_enc<<<NB, 256, 68608>>>();
    k_dec<<<NB, 256, 227328>>>();
    k_gen<<<dim3(NCB, DST), 256, GEN_SMEM>>>(out);
    k_lse<<<(GROWS+255)/256, 256>>>();
    k_fix<<<dim3(30, GROWS), 256>>>(out);
    k_row0<<<(NB*TRGV/4+255)/256, 256>>>(out);
}

// round 12
// speedup vs baseline: 1.3592x; 1.1439x over previous
#include <cuda_runtime.h>
#include <cuda_bf16.h>
#include <math.h>
#include <stdint.h>

#define SRCL  50
#define NB    128
#define TRGV  30000
#define NPV   30080
#define NCB   235
#define DST   39
#define GROWS 4992

// ----------------------------- device scratch -------------------------------
__device__ __align__(16) float          g_xin[2*SRCL*NB*256];
__device__ __align__(16) float          g_encout[SRCL*NB*128];
__device__ __align__(16) float          g_h0[NB*128];
__device__ __align__(16) float          g_c0[NB*128];
__device__ __align__(16) float          g_dpre[DST*NB*512];
__device__ __align__(16) __nv_bfloat16  g_hall[GROWS*128];
__device__ __align__(16) __nv_bfloat16  g_genW[NPV*128];
__device__ __align__(16) float          g_genb[NPV];
__device__ __align__(16) unsigned       g_Wip[64*128];     // attn_Wi  [k2][d]
__device__ __align__(16) unsigned       g_Wop[128*128];    // attn_Wo  [k2][j]
__device__ __align__(16) unsigned       g_whhp[64*512];    // dec_w_hh [k2][j]
__device__ __align__(16) unsigned       g_wihAp[64*512];   // dec_w_ih[:, :128] [k2][j]
__device__ __align__(16) unsigned       g_ewhh[2*32*256];  // enc_w_hh packed [dir][k2][j]
__device__ __align__(16) float          g_part[NCB*GROWS];
__device__ __align__(16) float          g_lse[GROWS];
__device__ __align__(16) __nv_bfloat16  g_logit[(size_t)GROWS*NPV];   // 300 MB bf16 logits

// ----------------------------- helpers --------------------------------------
__device__ __forceinline__ unsigned pk2(float a, float b){
    __nv_bfloat162 h = __floats2bfloat162_rn(a, b);
    return *reinterpret_cast<unsigned*>(&h);
}
__device__ __forceinline__ float2 up2(unsigned u){
    __nv_bfloat162 h = *reinterpret_cast<__nv_bfloat162*>(&u);
    return __bfloat1622float2(h);
}
__device__ __forceinline__ float sigf(float x){
    return __fdividef(1.f, 1.f + __expf(-x));
}
__device__ __forceinline__ float tanh_(float x){
    float xc = fminf(15.f, fmaxf(-15.f, x));
    float e  = __expf(2.f*xc);
    return __fdividef(e - 1.f, e + 1.f);
}
__device__ __forceinline__ void mma16816(float* d, const unsigned* a, const unsigned* b){
    asm volatile("mma.sync.aligned.m16n8k16.row.col.f32.bf16.bf16.f32 "
        "{%0,%1,%2,%3}, {%4,%5,%6,%7}, {%8,%9}, {%0,%1,%2,%3};"
        : "+f"(d[0]), "+f"(d[1]), "+f"(d[2]), "+f"(d[3])
        : "r"(a[0]), "r"(a[1]), "r"(a[2]), "r"(a[3]), "r"(b[0]), "r"(b[1]));
}

// ---------------- merged prep: packing + embedding pre-gates -----------------
// grid ranges: [0,416) pack_small | [416,15456) pack_gen | [15456,16256) embpre
//              [16256,16880) dpre
__global__ void __launch_bounds__(256) k_prep(
    const int* __restrict__ src, const int* __restrict__ trg,
    const float* __restrict__ EEMB, const float* __restrict__ DEMB,
    const float* __restrict__ ewf,  const float* __restrict__ ewhf,
    const float* __restrict__ ebf,  const float* __restrict__ ewb,
    const float* __restrict__ ewhb, const float* __restrict__ ebb,
    const float* __restrict__ Wi,   const float* __restrict__ Wo,
    const float* __restrict__ dwih, const float* __restrict__ dwhh,
    const float* __restrict__ db,
    const float* __restrict__ genW, const float* __restrict__ genb)
{
    __shared__ float emb[16][32];
    int blk = blockIdx.x, tid = threadIdx.x;

    if(blk < 416){                                   // ---- pack small weights
        int idx = blk*256 + tid;
        if(idx < 8192){ int k2=idx>>7, d=idx&127;
            g_Wip[idx] = pk2(Wi[d*128+2*k2], Wi[d*128+2*k2+1]); return; }
        idx -= 8192;
        if(idx < 16384){ int k2=idx>>7, j=idx&127;
            g_Wop[idx] = pk2(Wo[j*256+2*k2], Wo[j*256+2*k2+1]); return; }
        idx -= 16384;
        if(idx < 32768){ int k2=idx>>9, j=idx&511;
            g_whhp[idx] = pk2(dwhh[j*128+2*k2], dwhh[j*128+2*k2+1]); return; }
        idx -= 32768;
        if(idx < 32768){ int k2=idx>>9, j=idx&511;
            g_wihAp[idx] = pk2(dwih[j*158+2*k2], dwih[j*158+2*k2+1]); return; }
        idx -= 32768;
        if(idx < 16384){ int dir=idx>>13, r=idx&8191, k2=r>>8, j=r&255;
            const float* w = dir ? ewhb : ewhf;
            g_ewhh[dir*8192 + k2*256 + j] = pk2(w[j*64+2*k2], w[j*64+2*k2+1]); }
        return;
    }
    blk -= 416;
    if(blk < 15040){                                 // ---- pack generator
        int idx = blk*256 + tid;                     // < NPV*128
        int n = idx>>7, k = idx&127;
        g_genW[idx] = __float2bfloat16(n < TRGV ? genW[n*128+k] : 0.f);
        if(idx < NPV) g_genb[idx] = (idx < TRGV) ? genb[idx] : -1e30f;
        return;
    }
    blk -= 15040;
    if(blk < 800){                                   // ---- encoder input gates
        int bi = blk>>3, b0 = (blk&7)*16;
        int dir = bi / SRCL, s = bi % SRCL;
        int j = tid;
        const float* w = dir ? ewb : ewf;
        float wr[30];
        #pragma unroll
        for(int e=0;e<30;e++) wr[e] = w[j*30+e];
        float bj = (dir ? ebb : ebf)[j];
        for(int i=tid;i<480;i+=256){
            int q=i/30, e=i%30; int tok = src[s*NB + b0 + q];
            emb[q][e] = EEMB[tok*30+e];
        }
        __syncthreads();
        #pragma unroll 4
        for(int q=0;q<16;q++){
            float a = bj;
            #pragma unroll
            for(int e=0;e<30;e++) a += wr[e]*emb[q][e];
            g_xin[((dir*SRCL+s)*NB + b0 + q)*256 + j] = a;
        }
        return;
    }
    blk -= 800;
    {                                                // ---- decoder pre-gates
        int t = blk>>4, sub = blk&15;
        int b0 = (sub>>1)*16;
        int j  = (sub&1)*256 + tid;
        float wr[30];
        #pragma unroll
        for(int e=0;e<30;e++) wr[e] = dwih[j*158 + 128 + e];
        float bj = db[j];
        for(int i=tid;i<480;i+=256){
            int q=i/30, e=i%30; int tok = trg[t*NB + b0 + q];
            emb[q][e] = DEMB[tok*30+e];
        }
        __syncthreads();
        #pragma unroll 4
        for(int q=0;q<16;q++){
            float a = bj;
            #pragma unroll
            for(int e=0;e<30;e++) a += wr[e]*emb[q][e];
            g_dpre[(t*NB + b0 + q)*512 + j] = a;
        }
        return;
    }
}

// ------------------------------- encoder recurrence --------------------------
__global__ void k_enc()
{
    extern __shared__ char sm[];
    unsigned* ws = (unsigned*)sm;                       // 16384 u (64KB)
    float* hs = (float*)(sm + 65536);                   // 128
    float* cs = hs + 128;                               // 128
    float* gb = cs + 128;                               // 512
    int b = blockIdx.x, tid = threadIdx.x;

    { uint4* d4=(uint4*)ws; const uint4* s4=(const uint4*)g_ewhh;
      for(int i=tid;i<4096;i+=256) d4[i]=s4[i]; }
    if(tid < 128){ hs[tid]=0.f; cs[tid]=0.f; }
    __syncthreads();

    for(int t=0;t<SRCL;t++){
        float af = g_xin[((0*SRCL + t        )*NB+b)*256 + tid];
        float ab = g_xin[((1*SRCL + (SRCL-1-t))*NB+b)*256 + tid];
        #pragma unroll 8
        for(int k2=0;k2<32;k2++){
            float h0 = hs[2*k2], h1 = hs[2*k2+1];
            float2 wf2 = up2(ws[k2*256 + tid]);
            af += h0*wf2.x + h1*wf2.y;
            float g0 = hs[64+2*k2], g1 = hs[64+2*k2+1];
            float2 wb2 = up2(ws[8192 + k2*256 + tid]);
            ab += g0*wb2.x + g1*wb2.y;
        }
        gb[tid] = af; gb[256+tid] = ab;
        __syncthreads();
        if(tid < 128){
            int dir = tid>>6, d = tid&63;
            float* g = gb + dir*256;
            float iv=g[d], fv=g[64+d], gv=g[128+d], ov=g[192+d];
            float cn = sigf(fv)*cs[dir*64+d] + sigf(iv)*tanh_(gv);
            float hn = sigf(ov)*tanh_(cn);
            cs[dir*64+d]=cn; hs[dir*64+d]=hn;
            int s_out = dir ? (SRCL-1-t) : t;
            g_encout[(s_out*NB+b)*128 + dir*64 + d] = hn;
        }
        __syncthreads();
    }
    if(tid < 64){
        g_h0[b*128+2*tid]   = hs[tid];
        g_h0[b*128+2*tid+1] = hs[64+tid];
        g_c0[b*128+2*tid]   = cs[tid];
        g_c0[b*128+2*tid+1] = cs[64+tid];
    }
}

// ------------------------------- decoder recurrence --------------------------
__global__ void k_dec()
{
    extern __shared__ char sm[];
    unsigned* whh  = (unsigned*)sm;                 // 32768 u  @0
    unsigned* wop  = (unsigned*)(sm + 131072);      // 16384 u
    float*    encs = (float*)  (sm + 196608);       // 6400 f
    float*    h    = (float*)  (sm + 222208);       // 128
    float*    c    = h   + 128;
    float*    semi = c   + 128;
    float*    st   = semi+ 128;
    float*    ct   = st  + 128;
    float*    es   = ct  + 128;                     // 64
    float*    sc   = es  + 64;                      // 64
    float*    gb   = sc  + 64;                      // 512
    int b = blockIdx.x, tid = threadIdx.x;
    int lane = tid & 31, w = tid >> 5;

    { uint4* d4=(uint4*)whh; const uint4* s4=(const uint4*)g_whhp;
      for(int i=tid;i<8192;i+=256) d4[i]=s4[i]; }
    { uint4* d4=(uint4*)wop; const uint4* s4=(const uint4*)g_Wop;
      for(int i=tid;i<4096;i+=256) d4[i]=s4[i]; }
    { float4* d4=(float4*)encs; const float4* s4=(const float4*)g_encout;
      for(int i=tid;i<1600;i+=256){ int s=i>>5, r=i&31; d4[i]=s4[(s*NB+b)*32 + r]; } }
    if(tid < 128){ h[tid]=g_h0[b*128+tid]; c[tid]=g_c0[b*128+tid]; }
    __syncthreads();

    for(int t=0;t<DST;t++){
        if(tid < 128){
            float a = 0.f;
            #pragma unroll 8
            for(int k2=0;k2<64;k2++){
                float2 w2 = up2(__ldg(&g_Wip[k2*128 + tid]));
                a += h[2*k2]*w2.x + h[2*k2+1]*w2.y;
            }
            semi[tid] = a;
        }
        __syncthreads();
        for(int s=w; s<SRCL; s+=8){
            const float* er = encs + s*128;
            float a = er[lane]*semi[lane] + er[lane+32]*semi[lane+32]
                    + er[lane+64]*semi[lane+64] + er[lane+96]*semi[lane+96];
            #pragma unroll
            for(int o=16;o>0;o>>=1) a += __shfl_xor_sync(0xffffffffu, a, o);
            if(lane==0) es[s] = a;
        }
        __syncthreads();
        if(w == 0){
            float v0 = (lane    < SRCL) ? es[lane]    : -1e30f;
            float v1 = (lane+32 < SRCL) ? es[lane+32] : -1e30f;
            float m = fmaxf(v0, v1);
            #pragma unroll
            for(int o=16;o>0;o>>=1) m = fmaxf(m, __shfl_xor_sync(0xffffffffu, m, o));
            float e0 = (lane    < SRCL) ? __expf(v0-m) : 0.f;
            float e1 = (lane+32 < SRCL) ? __expf(v1-m) : 0.f;
            float ssum = e0 + e1;
            #pragma unroll
            for(int o=16;o>0;o>>=1) ssum += __shfl_xor_sync(0xffffffffu, ssum, o);
            float inv = __fdividef(1.f, ssum);
            if(lane    < SRCL) sc[lane]    = e0*inv;
            if(lane+32 < SRCL) sc[lane+32] = e1*inv;
        }
        __syncthreads();
        if(tid < 128){
            float a = 0.f;
            #pragma unroll 10
            for(int s=0;s<SRCL;s++) a += sc[s]*encs[s*128 + tid];
            st[tid] = a;
        }
        __syncthreads();
        if(tid < 128){
            float a = 0.f;
            #pragma unroll 8
            for(int k2=0;k2<64;k2++){
                float2 w2 = up2(wop[k2*128 + tid]);
                a += st[2*k2]*w2.x + st[2*k2+1]*w2.y;
            }
            #pragma unroll 8
            for(int k2=0;k2<64;k2++){
                float2 w2 = up2(wop[(64+k2)*128 + tid]);
                a += h[2*k2]*w2.x + h[2*k2+1]*w2.y;
            }
            ct[tid] = tanh_(a);
        }
        __syncthreads();
        {
            const float* pre = g_dpre + (t*NB+b)*512;
            float a0 = __ldg(&pre[tid]);
            float a1 = __ldg(&pre[tid+256]);
            #pragma unroll 4
            for(int k2=0;k2<64;k2++){
                float x0 = ct[2*k2], x1 = ct[2*k2+1];
                float2 wA0 = up2(__ldg(&g_wihAp[k2*512 + tid]));
                float2 wA1 = up2(__ldg(&g_wihAp[k2*512 + tid + 256]));
                a0 += x0*wA0.x + x1*wA0.y;
                a1 += x0*wA1.x + x1*wA1.y;
                float y0 = h[2*k2], y1 = h[2*k2+1];
                float2 wH0 = up2(whh[k2*512 + tid]);
                float2 wH1 = up2(whh[k2*512 + tid + 256]);
                a0 += y0*wH0.x + y1*wH0.y;
                a1 += y0*wH1.x + y1*wH1.y;
            }
            gb[tid] = a0; gb[tid+256] = a1;
        }
        __syncthreads();
        if(tid < 128){
            float iv=gb[tid], fv=gb[128+tid], gv=gb[256+tid], ov=gb[384+tid];
            float cn = sigf(fv)*c[tid] + sigf(iv)*tanh_(gv);
            float hn = sigf(ov)*tanh_(cn);
            c[tid]=cn; h[tid]=hn;
            g_hall[(t*NB+b)*128 + tid] = __float2bfloat16(hn);
        }
        __syncthreads();
    }
}

// ------------------- generator GEMM (mma.sync, single pass) ------------------
// CTA: 128(M) x 128(N), K=128 resident. Logits stored bf16 to g_logit.
#define GP 136
#define CP 132
__global__ void __launch_bounds__(256) k_gen()
{
    extern __shared__ char sm[];
    __nv_bfloat16* As = (__nv_bfloat16*)sm;
    __nv_bfloat16* Bs = As + 128*GP;
    int tid = threadIdx.x, w = tid>>5, lane = tid&31;
    int mb = blockIdx.y, nb = blockIdx.x;

    const uint4* Asrc = (const uint4*)(g_hall + (size_t)mb*128*128);
    const uint4* Bsrc = (const uint4*)(g_genW + (size_t)nb*128*128);
    for(int i=tid;i<2048;i+=256){
        int r=i>>4, c=i&15;
        *(uint4*)(As + r*GP + c*8) = Asrc[i];
    }
    for(int i=tid;i<2048;i+=256){
        int r=i>>4, c=i&15;
        *(uint4*)(Bs + r*GP + c*8) = Bsrc[i];
    }
    __syncthreads();

    int wm = w & 3, wn = w >> 2;                    // warp grid 4x2
    int m0 = wm*32, n0 = wn*64;
    int lq = lane>>2, lr = lane&3;

    float acc[2][8][4];
    #pragma unroll
    for(int mi=0;mi<2;mi++)
        #pragma unroll
        for(int ni=0;ni<8;ni++)
            #pragma unroll
            for(int q=0;q<4;q++) acc[mi][ni][q] = 0.f;

    const __nv_bfloat16* Ab = As + (m0+lq)*GP + 2*lr;
    const __nv_bfloat16* Bb = Bs + (n0+lq)*GP + 2*lr;

    #pragma unroll
    for(int ks=0;ks<8;ks++){
        int k0 = ks*16;
        unsigned a[2][4];
        #pragma unroll
        for(int mi=0;mi<2;mi++){
            const __nv_bfloat16* p = Ab + mi*16*GP + k0;
            a[mi][0] = *(const unsigned*)(p);
            a[mi][1] = *(const unsigned*)(p + 8*GP);
            a[mi][2] = *(const unsigned*)(p + 8);
            a[mi][3] = *(const unsigned*)(p + 8*GP + 8);
        }
        #pragma unroll
        for(int ni=0;ni<8;ni++){
            unsigned bfr[2];
            const __nv_bfloat16* p = Bb + ni*8*GP + k0;
            bfr[0] = *(const unsigned*)(p);
            bfr[1] = *(const unsigned*)(p + 8);
            mma16816(acc[0][ni], a[0], bfr);
            mma16816(acc[1][ni], a[1], bfr);
        }
    }
    __syncthreads();                                 // before smem reuse as C

    float* Cs = (float*)sm;
    #pragma unroll
    for(int mi=0;mi<2;mi++){
        #pragma unroll
        for(int ni=0;ni<8;ni++){
            float* cr = Cs + (m0+mi*16+lq)*CP + n0 + ni*8 + 2*lr;
            cr[0] = acc[mi][ni][0]; cr[1] = acc[mi][ni][1];
            cr[8*CP] = acc[mi][ni][2]; cr[8*CP+1] = acc[mi][ni][3];
        }
    }
    __syncthreads();

    // epilogue: warp per row, lane covers 4 cols; bf16 logits + f32 exp sums
    float4 bias = *(const float4*)(g_genb + nb*128 + lane*4);
    __nv_bfloat16* lbase = g_logit + (size_t)(mb*128)*NPV + nb*128 + lane*4;
    #pragma unroll 4
    for(int rr=0; rr<16; rr++){
        int r = w*16 + rr;
        const float* row = Cs + r*CP + lane*4;
        float v0 = row[0] + bias.x;
        float v1 = row[1] + bias.y;
        float v2 = row[2] + bias.z;
        float v3 = row[3] + bias.w;
        float s = __expf(v0) + __expf(v1) + __expf(v2) + __expf(v3);
        #pragma unroll
        for(int o=16;o>0;o>>=1) s += __shfl_xor_sync(0xffffffffu, s, o);
        if(lane == 0) g_part[nb*GROWS + mb*128 + r] = s;
        __nv_bfloat162 p0 = __floats2bfloat162_rn(v0, v1);
        __nv_bfloat162 p1 = __floats2bfloat162_rn(v2, v3);
        uint2 pk;
        pk.x = *reinterpret_cast<unsigned*>(&p0);
        pk.y = *reinterpret_cast<unsigned*>(&p1);
        *(uint2*)(lbase + (size_t)r*NPV) = pk;
    }
}

__global__ void k_lse()
{
    int m = blockIdx.x*256 + threadIdx.x;
    if(m >= GROWS) return;
    float s = 0.f;
    for(int nb=0;nb<NCB;nb++) s += g_part[nb*GROWS + m];
    g_lse[m] = logf(s);
}

// rows < NB: constant row0; rows >= NB: out = bf16logit - lse (streaming)
__global__ void __launch_bounds__(256) k_fixrow(float* __restrict__ out)
{
    int c8 = blockIdx.x*256 + threadIdx.x;           // 8 cols per thread
    if(c8 >= TRGV/8) return;                         // 3750
    int row = blockIdx.y;                            // 0..5119
    int c0 = c8*8;
    float* op = out + (size_t)row*TRGV + c0;
    if(row < NB){
        float4 A = make_float4(-1.f,-1.f,-1.f,-1.f);
        float4 B4 = A;
        if(c0 == 0) A.z = 0.f;                       // col 2
        *(float4*)op = A;
        *(float4*)(op+4) = B4;
    } else {
        int m = row - NB;
        float l = __ldg(&g_lse[m]);
        uint4 pk = *(const uint4*)(g_logit + (size_t)m*NPV + c0);
        __nv_bfloat162 h0 = *reinterpret_cast<__nv_bfloat162*>(&pk.x);
        __nv_bfloat162 h1 = *reinterpret_cast<__nv_bfloat162*>(&pk.y);
        __nv_bfloat162 h2 = *reinterpret_cast<__nv_bfloat162*>(&pk.z);
        __nv_bfloat162 h3 = *reinterpret_cast<__nv_bfloat162*>(&pk.w);
        float2 f0 = __bfloat1622float2(h0);
        float2 f1 = __bfloat1622float2(h1);
        float2 f2 = __bfloat1622float2(h2);
        float2 f3 = __bfloat1622float2(h3);
        float4 A  = make_float4(f0.x - l, f0.y - l, f1.x - l, f1.y - l);
        float4 B4 = make_float4(f2.x - l, f2.y - l, f3.x - l, f3.y - l);
        *(float4*)op = A;
        *(float4*)(op+4) = B4;
    }
}

// ----------------------------- launcher --------------------------------------
extern "C" void kernel_launch(void* const* d_in, const int* in_sizes, int n_in,
                              void* d_out, int out_size)
{
    const int*   src  = (const int*)  d_in[0];
    const int*   trg  = (const int*)  d_in[1];
    const float* EEMB = (const float*)d_in[3];
    const float* DEMB = (const float*)d_in[4];
    const float* ewf  = (const float*)d_in[5];
    const float* ewhf = (const float*)d_in[6];
    const float* ebf  = (const float*)d_in[7];
    const float* ewb  = (const float*)d_in[8];
    const float* ewhb = (const float*)d_in[9];
    const float* ebb  = (const float*)d_in[10];
    const float* Wi   = (const float*)d_in[11];
    const float* Wo   = (const float*)d_in[12];
    const float* dwih = (const float*)d_in[13];
    const float* dwhh = (const float*)d_in[14];
    const float* db   = (const float*)d_in[15];
    const float* genW = (const float*)d_in[16];
    const float* genb = (const float*)d_in[17];
    float* out = (float*)d_out;

    const int GEN_SMEM = 128*GP*2*2;                 // 69632 B

    cudaFuncSetAttribute(k_enc, cudaFuncAttributeMaxDynamicSharedMemorySize, 68608);
    cudaFuncSetAttribute(k_dec, cudaFuncAttributeMaxDynamicSharedMemorySize, 227328);
    cudaFuncSetAttribute(k_gen, cudaFuncAttributeMaxDynamicSharedMemorySize, GEN_SMEM);

    k_prep<<<16880, 256>>>(src, trg, EEMB, DEMB, ewf, ewhf, ebf, ewb, ewhb, ebb,
                           Wi, Wo, dwih, dwhh, db, genW, genb);
    k_enc<<<NB, 256, 68608>>>();
    k_dec<<<NB, 256, 227328>>>();
    k_gen<<<dim3(NCB, DST), 256, GEN_SMEM>>>();
    k_lse<<<(GROWS+255)/256, 256>>>();
    k_fixrow<<<dim3(15, 5120), 256>>>(out);
}